// round 3
// baseline (speedup 1.0000x reference)
#include <cuda_runtime.h>
#include <cuda_fp16.h>
#include <mma.h>

using namespace nvcuda;

// Problem dims
#define NB 512
#define NT 64
#define ND 128
#define NH 128

// ---------------- static device scratch (no runtime allocation) ----------------
__device__ float  g_alpha[128];
__device__ float  g_Xa[NB * NT * ND];           // X_attri fp32, [b][t][d]
__device__ __half g_Xh[NB * NT * ND];           // X_attri fp16
__device__ __half g_wihh[512 * 128];            // w_ih fp16, same layout [g][d]
__device__ __half g_whhT[128 * 512];            // w_hh transposed fp16 [k][g]
__device__ __half g_W1hc[256 * 128];            // w_a1 rows 0..255 fp16 [j][n]
__device__ __half g_W1x[64 * 128];              // w_a1 rows 256..319 fp16 [t][n]
__device__ float  g_bsum[512];                  // b_ih + b_hh
__device__ float  g_gih[(size_t)NB * NT * 512]; // X_attri @ w_ih^T (no bias)
__device__ __half g_XpW[(size_t)NB * 128 * 128];// [b][d][k] fp16

// ---------------- math helpers ----------------
__device__ __forceinline__ float tanh_fast(float x) {
    float y; asm("tanh.approx.f32 %0, %1;" : "=f"(y) : "f"(x)); return y;
}
__device__ __forceinline__ float sigmoidf_(float x) {
    return 1.f / (1.f + __expf(-x));
}
__device__ __forceinline__ float tanh_acc(float x) {
    x = fminf(fmaxf(x, -15.f), 15.f);
    float e2 = __expf(-2.f * x);
    return (1.f - e2) / (1.f + e2);
}

// ---------------- K0: attribute attention -> g_alpha[128] ----------------
__global__ __launch_bounds__(128) void k_alpha(
    const float* __restrict__ attri, const float* __restrict__ w1,
    const float* __restrict__ b1, const float* __restrict__ w2,
    const float* __restrict__ b2)
{
    __shared__ float sv[128];
    __shared__ float sred;
    int d = threadIdx.x;
    float ar[64];
    #pragma unroll
    for (int t = 0; t < 64; ++t) ar[t] = attri[d * 64 + t];
    float s = b2[0];
    for (int j = 0; j < 32; ++j) {
        float a = b1[j];
        #pragma unroll
        for (int t = 0; t < 64; ++t) a = fmaf(ar[t], w1[t * 32 + j], a);
        a = (a > 0.f) ? a : 0.5f * a;           // LeakyReLU(0.5)
        s = fmaf(a, w2[j], s);
    }
    sv[d] = s; __syncthreads();
    if (d == 0) { float m = sv[0]; for (int i = 1; i < 128; ++i) m = fmaxf(m, sv[i]); sred = m; }
    __syncthreads();
    float ev = __expf(s - sred);
    sv[d] = ev; __syncthreads();
    if (d == 0) { float su = 0.f; for (int i = 0; i < 128; ++i) su += sv[i]; sred = su; }
    __syncthreads();
    g_alpha[d] = ev / sred;
}

// ---------------- K1: conversions / transposes ----------------
__global__ __launch_bounds__(256) void k_prep(
    const float* __restrict__ X, const float* __restrict__ w_ih,
    const float* __restrict__ w_hh, const float* __restrict__ w_a1,
    const float* __restrict__ b_ih, const float* __restrict__ b_hh)
{
    int i = blockIdx.x * 256 + threadIdx.x;
    if (i < NB * NT * ND) {
        float v = X[i] * g_alpha[i & 127];
        g_Xa[i] = v;
        g_Xh[i] = __float2half(v);
    }
    if (i < 65536) {
        g_wihh[i] = __float2half(w_ih[i]);
        int g = i >> 7, k = i & 127;
        g_whhT[k * 512 + g] = __float2half(w_hh[i]); // w_hh[g][k]
    }
    if (i < 32768) g_W1hc[i] = __float2half(w_a1[i]);
    if (i < 8192)  g_W1x[i]  = __float2half(w_a1[32768 + i]);
    if (i < 512)   g_bsum[i] = b_ih[i] + b_hh[i];
}

// ---------------- K2: gih[32768,512] = Xh[32768,128] @ w_ih^T ----------------
__global__ __launch_bounds__(256) void k_gih()
{
    int m0 = blockIdx.x * 16;
    int w = threadIdx.x >> 5;
    wmma::fragment<wmma::matrix_a, 16, 16, 16, __half, wmma::row_major> a[8];
    #pragma unroll
    for (int k = 0; k < 8; ++k)
        wmma::load_matrix_sync(a[k], g_Xh + (size_t)m0 * 128 + k * 16, 128);
    #pragma unroll
    for (int rep = 0; rep < 4; ++rep) {
        int n0 = w * 16 + rep * 128;
        wmma::fragment<wmma::accumulator, 16, 16, 16, float> c;
        wmma::fill_fragment(c, 0.f);
        #pragma unroll
        for (int k = 0; k < 8; ++k) {
            wmma::fragment<wmma::matrix_b, 16, 16, 16, __half, wmma::col_major> b;
            // B[k][n] = w_ih[n][k] -> col_major on [g][d] layout, ldm=128
            wmma::load_matrix_sync(b, g_wihh + (size_t)n0 * 128 + k * 16, 128);
            wmma::mma_sync(c, a[k], b, c);
        }
        wmma::store_matrix_sync(g_gih + (size_t)m0 * 512 + n0, c, 512, wmma::mem_row_major);
    }
}

// ---------------- K3: XpW[b][128,128] = Xp[b] @ W1x ----------------
__global__ __launch_bounds__(256) void k_xpw()
{
    __shared__ float cbuf[8][256];
    int b = blockIdx.x;
    int w = threadIdx.x >> 5, lane = threadIdx.x & 31;
    const __half* Ab = g_Xh + (size_t)b * (NT * ND); // element (d,t) at [t*128+d] -> col_major
    int m0 = w * 16;
    wmma::fragment<wmma::matrix_a, 16, 16, 16, __half, wmma::col_major> a[4];
    #pragma unroll
    for (int k = 0; k < 4; ++k)
        wmma::load_matrix_sync(a[k], Ab + k * 16 * 128 + m0, 128);
    for (int nt = 0; nt < 8; ++nt) {
        int n0 = nt * 16;
        wmma::fragment<wmma::accumulator, 16, 16, 16, float> c;
        wmma::fill_fragment(c, 0.f);
        #pragma unroll
        for (int k = 0; k < 4; ++k) {
            wmma::fragment<wmma::matrix_b, 16, 16, 16, __half, wmma::row_major> bb;
            wmma::load_matrix_sync(bb, g_W1x + k * 16 * 128 + n0, 128);
            wmma::mma_sync(c, a[k], bb, c);
        }
        wmma::store_matrix_sync(cbuf[w], c, 16, wmma::mem_row_major);
        __syncwarp();
        #pragma unroll
        for (int j = 0; j < 8; ++j) {
            int idx = j * 32 + lane;
            int r = idx >> 4, cl = idx & 15;
            g_XpW[(size_t)b * 16384 + (size_t)(m0 + r) * 128 + n0 + cl] =
                __float2half(cbuf[w][idx]);
        }
        __syncwarp();
    }
}

// ---------------- K4: persistent sequential scan ----------------
// smem layout (bytes)
#define OFF_WHHT 0
#define OFF_W1HC 131072
#define OFF_HA   196608
#define OFF_CA   200704
#define OFF_GSCR 204800
#define OFF_VBUF 212992
#define OFF_TMPA 215040
#define OFF_TMPB 217088
#define OFF_SHH  219136
#define OFF_SHC  221184
#define OFF_BSUM 223232
#define OFF_BA1  225280
#define OFF_WA2  225792
#define OFF_RED  226304
#define OFF_RED2 226368
#define SMEM_TOTAL 226432

__device__ __forceinline__ void mma_chunk(
    int chunk, int warp, const __half* s_whhT, const __half* s_W1hc,
    const __half* s_hA, const __half* s_cA, float* s_gscr)
{
    if (warp >= 8) return;
    wmma::fragment<wmma::accumulator, 16, 16, 16, float> cf;
    wmma::fill_fragment(cf, 0.f);
    wmma::fragment<wmma::matrix_a, 16, 16, 16, __half, wmma::row_major> af;
    wmma::fragment<wmma::matrix_b, 16, 16, 16, __half, wmma::row_major> bf;
    if (chunk < 4) {
        const __half* B0 = s_whhT + chunk * 128 + warp * 16;
        #pragma unroll
        for (int k = 0; k < 8; ++k) {
            wmma::load_matrix_sync(af, s_hA + k * 16, 128);
            wmma::load_matrix_sync(bf, B0 + k * 16 * 512, 512);
            wmma::mma_sync(cf, af, bf, cf);
        }
    } else {
        const __half* B0 = s_W1hc + warp * 16;
        #pragma unroll
        for (int k = 0; k < 16; ++k) {
            const __half* Ap = (k < 8) ? (s_hA + k * 16) : (s_cA + (k - 8) * 16);
            wmma::load_matrix_sync(af, Ap, 128);
            wmma::load_matrix_sync(bf, B0 + k * 16 * 128, 128);
            wmma::mma_sync(cf, af, bf, cf);
        }
    }
    wmma::store_matrix_sync(s_gscr + warp * 16, cf, 128, wmma::mem_row_major);
}

__global__ __launch_bounds__(512, 1) void k_main(
    const float* __restrict__ b_a1, const float* __restrict__ w_a2,
    const float* __restrict__ b_a2p, float* __restrict__ out)
{
    extern __shared__ char sm[];
    __half* s_whhT = (__half*)(sm + OFF_WHHT);
    __half* s_W1hc = (__half*)(sm + OFF_W1HC);
    __half* s_hA   = (__half*)(sm + OFF_HA);
    __half* s_cA   = (__half*)(sm + OFF_CA);
    float*  s_gscr = (float*)(sm + OFF_GSCR);
    float*  s_vbuf = (float*)(sm + OFF_VBUF);
    float*  s_tmpA = (float*)(sm + OFF_TMPA);
    float*  s_tmpB = (float*)(sm + OFF_TMPB);
    float*  s_shh  = (float*)(sm + OFF_SHH);
    float*  s_shc  = (float*)(sm + OFF_SHC);
    float*  s_bsum = (float*)(sm + OFF_BSUM);
    float*  s_ba1  = (float*)(sm + OFF_BA1);
    float*  s_wa2  = (float*)(sm + OFF_WA2);
    float*  s_red  = (float*)(sm + OFF_RED);
    float*  s_red2 = (float*)(sm + OFF_RED2);

    const int tid = threadIdx.x;
    const int warp = tid >> 5;
    const int b0 = blockIdx.x * 4;
    const float b_a2 = b_a2p[0];

    // ---- load weights to smem (vectorized) ----
    {
        const uint4* src = (const uint4*)g_whhT; uint4* dst = (uint4*)s_whhT;
        #pragma unroll
        for (int i = tid; i < 8192; i += 512) dst[i] = src[i];
        const uint4* src2 = (const uint4*)g_W1hc; uint4* dst2 = (uint4*)s_W1hc;
        #pragma unroll
        for (int i = tid; i < 4096; i += 512) dst2[i] = src2[i];
        uint4 z; z.x = z.y = z.z = z.w = 0u;
        uint4* ha = (uint4*)s_hA; uint4* ca = (uint4*)s_cA;
        if (tid < 256) { ha[tid] = z; ca[tid] = z; }
        s_shh[tid] = 0.f; s_shc[tid] = 0.f;
        s_bsum[tid] = g_bsum[tid];
        if (tid < 128) { s_ba1[tid] = b_a1[tid]; s_wa2[tid] = w_a2[tid]; }
    }
    __syncthreads();

    const int b4 = tid >> 7;   // 0..3
    const int i  = tid & 127;  // 0..127
    const size_t gb = (size_t)(b0 + b4) * 64;

    for (int t = 0; t < 64; ++t) {
        const size_t grow = (gb + t) * 512;

        // ---- chunk v (index 4): v = [h|c] @ W1hc ----
        mma_chunk(4, warp, s_whhT, s_W1hc, s_hA, s_cA, s_gscr);
        __syncthreads();
        s_vbuf[tid] = s_gscr[tid] + s_ba1[i];
        __syncthreads();

        // ---- chunk 0: i-gate ----
        mma_chunk(0, warp, s_whhT, s_W1hc, s_hA, s_cA, s_gscr);
        __syncthreads();
        {
            float raw = s_gscr[tid] + g_gih[grow + i] + s_bsum[i];
            s_tmpA[tid] = sigmoidf_(raw);
        }
        __syncthreads();

        // ---- chunk 1: f-gate ----
        mma_chunk(1, warp, s_whhT, s_W1hc, s_hA, s_cA, s_gscr);
        __syncthreads();
        {
            float raw = s_gscr[tid] + g_gih[grow + 128 + i] + s_bsum[128 + i];
            s_tmpB[tid] = sigmoidf_(raw) * s_shc[tid];
        }
        __syncthreads();

        // ---- chunk 2: g-gate -> new c ----
        mma_chunk(2, warp, s_whhT, s_W1hc, s_hA, s_cA, s_gscr);
        __syncthreads();
        {
            float raw = s_gscr[tid] + g_gih[grow + 256 + i] + s_bsum[256 + i];
            float cn = s_tmpB[tid] + s_tmpA[tid] * tanh_acc(raw);
            s_shc[tid] = cn;
            s_cA[b4 * 128 + i] = __float2half(cn);
        }
        __syncthreads();

        // ---- chunk 3: o-gate -> new h ----
        mma_chunk(3, warp, s_whhT, s_W1hc, s_hA, s_cA, s_gscr);
        __syncthreads();
        {
            float raw = s_gscr[tid] + g_gih[grow + 384 + i] + s_bsum[384 + i];
            float hn = sigmoidf_(raw) * tanh_acc(s_shc[tid]);
            s_shh[tid] = hn;
            s_hA[b4 * 128 + i] = __float2half(hn);
        }
        __syncthreads();

        // ---- phase B: e, softmax over d, output (uses vbuf = old-state v) ----
        {
            const __half2* xp = (const __half2*)(g_XpW + ((size_t)(b0 + b4) * 128 + i) * 128);
            const float2* vv2 = (const float2*)(s_vbuf + b4 * 128);
            const float2* wv2 = (const float2*)s_wa2;
            float acc = b_a2;
            #pragma unroll 8
            for (int k2 = 0; k2 < 64; ++k2) {
                float2 xv = __half22float2(xp[k2]);
                float2 vv = vv2[k2];
                float2 wv = wv2[k2];
                acc = fmaf(tanh_fast(xv.x + vv.x), wv.x, acc);
                acc = fmaf(tanh_fast(xv.y + vv.y), wv.y, acc);
            }
            // softmax over d within the 128-thread group of this batch
            float m = acc;
            #pragma unroll
            for (int o = 16; o > 0; o >>= 1) m = fmaxf(m, __shfl_xor_sync(0xffffffffu, m, o));
            int wig = (tid >> 5) & 3;
            if ((tid & 31) == 0) s_red[b4 * 4 + wig] = m;
            __syncthreads();
            float gm = fmaxf(fmaxf(s_red[b4 * 4], s_red[b4 * 4 + 1]),
                             fmaxf(s_red[b4 * 4 + 2], s_red[b4 * 4 + 3]));
            float ex = __expf(acc - gm);
            float ssum = ex;
            #pragma unroll
            for (int o = 16; o > 0; o >>= 1) ssum += __shfl_xor_sync(0xffffffffu, ssum, o);
            if ((tid & 31) == 0) s_red2[b4 * 4 + wig] = ssum;
            __syncthreads();
            float tot = s_red2[b4 * 4] + s_red2[b4 * 4 + 1] +
                        s_red2[b4 * 4 + 2] + s_red2[b4 * 4 + 3];
            float al = ex / tot;
            size_t oidx = (gb + t) * 128 + i;
            out[oidx] = al * g_Xa[oidx];
        }
        // next iteration's first __syncthreads (after mma_chunk) orders vbuf reuse
        __syncthreads();
    }
}

// ---------------- launch ----------------
extern "C" void kernel_launch(void* const* d_in, const int* in_sizes, int n_in,
                              void* d_out, int out_size)
{
    const float* X      = (const float*)d_in[0];
    const float* attri  = (const float*)d_in[1];
    const float* w_at1  = (const float*)d_in[2];
    const float* b_at1  = (const float*)d_in[3];
    const float* w_at2  = (const float*)d_in[4];
    const float* b_at2  = (const float*)d_in[5];
    const float* w_a1   = (const float*)d_in[6];
    const float* b_a1   = (const float*)d_in[7];
    const float* w_a2   = (const float*)d_in[8];
    const float* b_a2   = (const float*)d_in[9];
    const float* w_ih   = (const float*)d_in[10];
    const float* w_hh   = (const float*)d_in[11];
    const float* b_ih   = (const float*)d_in[12];
    const float* b_hh   = (const float*)d_in[13];
    float* out = (float*)d_out;

    cudaFuncSetAttribute(k_main, cudaFuncAttributeMaxDynamicSharedMemorySize, SMEM_TOTAL);

    k_alpha<<<1, 128>>>(attri, w_at1, b_at1, w_at2, b_at2);
    k_prep<<<(NB * NT * ND + 255) / 256, 256>>>(X, w_ih, w_hh, w_a1, b_ih, b_hh);
    k_gih<<<(NB * NT) / 16 * 1, 256>>>();   // 2048 blocks of 16 rows
    k_xpw<<<NB, 256>>>();
    k_main<<<128, 512, SMEM_TOTAL>>>(b_a1, w_a2, b_a2, out);
}

// round 4
// speedup vs baseline: 1.0035x; 1.0035x over previous
#include <cuda_runtime.h>
#include <cuda_fp16.h>
#include <mma.h>

using namespace nvcuda;

// Problem dims
#define NB 512
#define NT 64
#define ND 128
#define NH 128

// ---------------- static device scratch (no runtime allocation) ----------------
__device__ float  g_alpha[128];
__device__ float  g_Xa[NB * NT * ND];           // X_attri fp32, [b][t][d]
__device__ __half g_Xh[NB * NT * ND];           // X_attri fp16
__device__ __half g_wihh[512 * 128];            // w_ih fp16, same layout [g][d]
__device__ __half g_whhT[128 * 512];            // w_hh transposed fp16 [k][g]
__device__ __half g_W1hc[256 * 128];            // w_a1 rows 0..255 fp16 [j][n]
__device__ __half g_W1x[64 * 128];              // w_a1 rows 256..319 fp16 [t][n]
__device__ float  g_bsum[512];                  // b_ih + b_hh
__device__ float  g_gih[(size_t)NB * NT * 512]; // X_attri @ w_ih^T (no bias)
__device__ __half g_XpW[(size_t)NB * 128 * 128];// [b][d][k] fp16

// ---------------- math helpers ----------------
__device__ __forceinline__ float tanh_fast(float x) {
    float y; asm("tanh.approx.f32 %0, %1;" : "=f"(y) : "f"(x)); return y;
}
__device__ __forceinline__ float sigmoidf_(float x) {
    return 1.f / (1.f + __expf(-x));
}
__device__ __forceinline__ float tanh_acc(float x) {
    x = fminf(fmaxf(x, -15.f), 15.f);
    float e2 = __expf(-2.f * x);
    return (1.f - e2) / (1.f + e2);
}

// ---------------- K0: attribute attention -> g_alpha[128] ----------------
__global__ __launch_bounds__(128) void k_alpha(
    const float* __restrict__ attri, const float* __restrict__ w1,
    const float* __restrict__ b1, const float* __restrict__ w2,
    const float* __restrict__ b2)
{
    __shared__ float sv[128];
    __shared__ float sred;
    int d = threadIdx.x;
    float ar[64];
    #pragma unroll
    for (int t = 0; t < 64; ++t) ar[t] = attri[d * 64 + t];
    float s = b2[0];
    for (int j = 0; j < 32; ++j) {
        float a = b1[j];
        #pragma unroll
        for (int t = 0; t < 64; ++t) a = fmaf(ar[t], w1[t * 32 + j], a);
        a = (a > 0.f) ? a : 0.5f * a;           // LeakyReLU(0.5)
        s = fmaf(a, w2[j], s);
    }
    sv[d] = s; __syncthreads();
    if (d == 0) { float m = sv[0]; for (int i = 1; i < 128; ++i) m = fmaxf(m, sv[i]); sred = m; }
    __syncthreads();
    float ev = __expf(s - sred);
    sv[d] = ev; __syncthreads();
    if (d == 0) { float su = 0.f; for (int i = 0; i < 128; ++i) su += sv[i]; sred = su; }
    __syncthreads();
    g_alpha[d] = ev / sred;
}

// ---------------- K1: conversions / transposes ----------------
__global__ __launch_bounds__(256) void k_prep(
    const float* __restrict__ X, const float* __restrict__ w_ih,
    const float* __restrict__ w_hh, const float* __restrict__ w_a1,
    const float* __restrict__ b_ih, const float* __restrict__ b_hh)
{
    int i = blockIdx.x * 256 + threadIdx.x;
    if (i < NB * NT * ND) {
        float v = X[i] * g_alpha[i & 127];
        g_Xa[i] = v;
        g_Xh[i] = __float2half(v);
    }
    if (i < 65536) {
        g_wihh[i] = __float2half(w_ih[i]);
        int g = i >> 7, k = i & 127;
        g_whhT[k * 512 + g] = __float2half(w_hh[i]); // w_hh[g][k]
    }
    if (i < 32768) g_W1hc[i] = __float2half(w_a1[i]);
    if (i < 8192)  g_W1x[i]  = __float2half(w_a1[32768 + i]);
    if (i < 512)   g_bsum[i] = b_ih[i] + b_hh[i];
}

// ---------------- K2: gih[32768,512] = Xh[32768,128] @ w_ih^T ----------------
__global__ __launch_bounds__(256) void k_gih()
{
    int m0 = blockIdx.x * 16;
    int w = threadIdx.x >> 5;
    wmma::fragment<wmma::matrix_a, 16, 16, 16, __half, wmma::row_major> a[8];
    #pragma unroll
    for (int k = 0; k < 8; ++k)
        wmma::load_matrix_sync(a[k], g_Xh + (size_t)m0 * 128 + k * 16, 128);
    #pragma unroll
    for (int rep = 0; rep < 4; ++rep) {
        int n0 = w * 16 + rep * 128;
        wmma::fragment<wmma::accumulator, 16, 16, 16, float> c;
        wmma::fill_fragment(c, 0.f);
        #pragma unroll
        for (int k = 0; k < 8; ++k) {
            wmma::fragment<wmma::matrix_b, 16, 16, 16, __half, wmma::col_major> b;
            // B[k][n] = w_ih[n][k] -> col_major on [g][d] layout, ldm=128
            wmma::load_matrix_sync(b, g_wihh + (size_t)n0 * 128 + k * 16, 128);
            wmma::mma_sync(c, a[k], b, c);
        }
        wmma::store_matrix_sync(g_gih + (size_t)m0 * 512 + n0, c, 512, wmma::mem_row_major);
    }
}

// ---------------- K3: XpW[b][128,128] = Xp[b] @ W1x ----------------
__global__ __launch_bounds__(256) void k_xpw()
{
    __shared__ float cbuf[8][256];
    int b = blockIdx.x;
    int w = threadIdx.x >> 5, lane = threadIdx.x & 31;
    const __half* Ab = g_Xh + (size_t)b * (NT * ND); // element (d,t) at [t*128+d] -> col_major
    int m0 = w * 16;
    wmma::fragment<wmma::matrix_a, 16, 16, 16, __half, wmma::col_major> a[4];
    #pragma unroll
    for (int k = 0; k < 4; ++k)
        wmma::load_matrix_sync(a[k], Ab + k * 16 * 128 + m0, 128);
    for (int nt = 0; nt < 8; ++nt) {
        int n0 = nt * 16;
        wmma::fragment<wmma::accumulator, 16, 16, 16, float> c;
        wmma::fill_fragment(c, 0.f);
        #pragma unroll
        for (int k = 0; k < 4; ++k) {
            wmma::fragment<wmma::matrix_b, 16, 16, 16, __half, wmma::row_major> bb;
            wmma::load_matrix_sync(bb, g_W1x + k * 16 * 128 + n0, 128);
            wmma::mma_sync(c, a[k], bb, c);
        }
        wmma::store_matrix_sync(cbuf[w], c, 16, wmma::mem_row_major);
        __syncwarp();
        #pragma unroll
        for (int j = 0; j < 8; ++j) {
            int idx = j * 32 + lane;
            int r = idx >> 4, cl = idx & 15;
            g_XpW[(size_t)b * 16384 + (size_t)(m0 + r) * 128 + n0 + cl] =
                __float2half(cbuf[w][idx]);
        }
        __syncwarp();
    }
}

// ---------------- K4: persistent sequential scan ----------------
// smem layout (bytes)
#define OFF_WHHT 0
#define OFF_W1HC 131072
#define OFF_HA   196608
#define OFF_CA   200704
#define OFF_GSCR 204800
#define OFF_VBUF 212992
#define OFF_TMPA 215040
#define OFF_TMPB 217088
#define OFF_SHH  219136
#define OFF_SHC  221184
#define OFF_BSUM 223232
#define OFF_BA1  225280
#define OFF_WA2  225792
#define OFF_RED  226304
#define OFF_RED2 226368
#define SMEM_TOTAL 226432

__device__ __forceinline__ void mma_chunk(
    int chunk, int warp, const __half* s_whhT, const __half* s_W1hc,
    const __half* s_hA, const __half* s_cA, float* s_gscr)
{
    if (warp >= 8) return;
    wmma::fragment<wmma::accumulator, 16, 16, 16, float> cf;
    wmma::fill_fragment(cf, 0.f);
    wmma::fragment<wmma::matrix_a, 16, 16, 16, __half, wmma::row_major> af;
    wmma::fragment<wmma::matrix_b, 16, 16, 16, __half, wmma::row_major> bf;
    if (chunk < 4) {
        const __half* B0 = s_whhT + chunk * 128 + warp * 16;
        #pragma unroll
        for (int k = 0; k < 8; ++k) {
            wmma::load_matrix_sync(af, s_hA + k * 16, 128);
            wmma::load_matrix_sync(bf, B0 + k * 16 * 512, 512);
            wmma::mma_sync(cf, af, bf, cf);
        }
    } else {
        const __half* B0 = s_W1hc + warp * 16;
        #pragma unroll
        for (int k = 0; k < 16; ++k) {
            const __half* Ap = (k < 8) ? (s_hA + k * 16) : (s_cA + (k - 8) * 16);
            wmma::load_matrix_sync(af, Ap, 128);
            wmma::load_matrix_sync(bf, B0 + k * 16 * 128, 128);
            wmma::mma_sync(cf, af, bf, cf);
        }
    }
    wmma::store_matrix_sync(s_gscr + warp * 16, cf, 128, wmma::mem_row_major);
}

__global__ __launch_bounds__(512, 1) void k_main(
    const float* __restrict__ b_a1, const float* __restrict__ w_a2,
    const float* __restrict__ b_a2p, float* __restrict__ out)
{
    extern __shared__ char sm[];
    __half* s_whhT = (__half*)(sm + OFF_WHHT);
    __half* s_W1hc = (__half*)(sm + OFF_W1HC);
    __half* s_hA   = (__half*)(sm + OFF_HA);
    __half* s_cA   = (__half*)(sm + OFF_CA);
    float*  s_gscr = (float*)(sm + OFF_GSCR);
    float*  s_vbuf = (float*)(sm + OFF_VBUF);
    float*  s_tmpA = (float*)(sm + OFF_TMPA);
    float*  s_tmpB = (float*)(sm + OFF_TMPB);
    float*  s_shh  = (float*)(sm + OFF_SHH);
    float*  s_shc  = (float*)(sm + OFF_SHC);
    float*  s_bsum = (float*)(sm + OFF_BSUM);
    float*  s_ba1  = (float*)(sm + OFF_BA1);
    float*  s_wa2  = (float*)(sm + OFF_WA2);
    float*  s_red  = (float*)(sm + OFF_RED);
    float*  s_red2 = (float*)(sm + OFF_RED2);

    const int tid = threadIdx.x;
    const int warp = tid >> 5;
    const int b0 = blockIdx.x * 4;
    const float b_a2 = b_a2p[0];

    // ---- load weights to smem (vectorized) ----
    {
        const uint4* src = (const uint4*)g_whhT; uint4* dst = (uint4*)s_whhT;
        #pragma unroll
        for (int i = tid; i < 8192; i += 512) dst[i] = src[i];
        const uint4* src2 = (const uint4*)g_W1hc; uint4* dst2 = (uint4*)s_W1hc;
        #pragma unroll
        for (int i = tid; i < 4096; i += 512) dst2[i] = src2[i];
        uint4 z; z.x = z.y = z.z = z.w = 0u;
        uint4* ha = (uint4*)s_hA; uint4* ca = (uint4*)s_cA;
        if (tid < 256) { ha[tid] = z; ca[tid] = z; }
        s_shh[tid] = 0.f; s_shc[tid] = 0.f;
        s_bsum[tid] = g_bsum[tid];
        if (tid < 128) { s_ba1[tid] = b_a1[tid]; s_wa2[tid] = w_a2[tid]; }
    }
    __syncthreads();

    const int b4 = tid >> 7;   // 0..3
    const int i  = tid & 127;  // 0..127
    const size_t gb = (size_t)(b0 + b4) * 64;

    for (int t = 0; t < 64; ++t) {
        const size_t grow = (gb + t) * 512;

        // ---- chunk v (index 4): v = [h|c] @ W1hc ----
        mma_chunk(4, warp, s_whhT, s_W1hc, s_hA, s_cA, s_gscr);
        __syncthreads();
        s_vbuf[tid] = s_gscr[tid] + s_ba1[i];
        __syncthreads();

        // ---- chunk 0: i-gate ----
        mma_chunk(0, warp, s_whhT, s_W1hc, s_hA, s_cA, s_gscr);
        __syncthreads();
        {
            float raw = s_gscr[tid] + g_gih[grow + i] + s_bsum[i];
            s_tmpA[tid] = sigmoidf_(raw);
        }
        __syncthreads();

        // ---- chunk 1: f-gate ----
        mma_chunk(1, warp, s_whhT, s_W1hc, s_hA, s_cA, s_gscr);
        __syncthreads();
        {
            float raw = s_gscr[tid] + g_gih[grow + 128 + i] + s_bsum[128 + i];
            s_tmpB[tid] = sigmoidf_(raw) * s_shc[tid];
        }
        __syncthreads();

        // ---- chunk 2: g-gate -> new c ----
        mma_chunk(2, warp, s_whhT, s_W1hc, s_hA, s_cA, s_gscr);
        __syncthreads();
        {
            float raw = s_gscr[tid] + g_gih[grow + 256 + i] + s_bsum[256 + i];
            float cn = s_tmpB[tid] + s_tmpA[tid] * tanh_acc(raw);
            s_shc[tid] = cn;
            s_cA[b4 * 128 + i] = __float2half(cn);
        }
        __syncthreads();

        // ---- chunk 3: o-gate -> new h ----
        mma_chunk(3, warp, s_whhT, s_W1hc, s_hA, s_cA, s_gscr);
        __syncthreads();
        {
            float raw = s_gscr[tid] + g_gih[grow + 384 + i] + s_bsum[384 + i];
            float hn = sigmoidf_(raw) * tanh_acc(s_shc[tid]);
            s_shh[tid] = hn;
            s_hA[b4 * 128 + i] = __float2half(hn);
        }
        __syncthreads();

        // ---- phase B: e, softmax over d, output (uses vbuf = old-state v) ----
        {
            const __half2* xp = (const __half2*)(g_XpW + ((size_t)(b0 + b4) * 128 + i) * 128);
            const float2* vv2 = (const float2*)(s_vbuf + b4 * 128);
            const float2* wv2 = (const float2*)s_wa2;
            float acc = b_a2;
            #pragma unroll 8
            for (int k2 = 0; k2 < 64; ++k2) {
                float2 xv = __half22float2(xp[k2]);
                float2 vv = vv2[k2];
                float2 wv = wv2[k2];
                acc = fmaf(tanh_fast(xv.x + vv.x), wv.x, acc);
                acc = fmaf(tanh_fast(xv.y + vv.y), wv.y, acc);
            }
            // softmax over d within the 128-thread group of this batch
            float m = acc;
            #pragma unroll
            for (int o = 16; o > 0; o >>= 1) m = fmaxf(m, __shfl_xor_sync(0xffffffffu, m, o));
            int wig = (tid >> 5) & 3;
            if ((tid & 31) == 0) s_red[b4 * 4 + wig] = m;
            __syncthreads();
            float gm = fmaxf(fmaxf(s_red[b4 * 4], s_red[b4 * 4 + 1]),
                             fmaxf(s_red[b4 * 4 + 2], s_red[b4 * 4 + 3]));
            float ex = __expf(acc - gm);
            float ssum = ex;
            #pragma unroll
            for (int o = 16; o > 0; o >>= 1) ssum += __shfl_xor_sync(0xffffffffu, ssum, o);
            if ((tid & 31) == 0) s_red2[b4 * 4 + wig] = ssum;
            __syncthreads();
            float tot = s_red2[b4 * 4] + s_red2[b4 * 4 + 1] +
                        s_red2[b4 * 4 + 2] + s_red2[b4 * 4 + 3];
            float al = ex / tot;
            size_t oidx = (gb + t) * 128 + i;
            out[oidx] = al * g_Xa[oidx];
        }
        // next iteration's first __syncthreads (after mma_chunk) orders vbuf reuse
        __syncthreads();
    }
}

// ---------------- launch ----------------
extern "C" void kernel_launch(void* const* d_in, const int* in_sizes, int n_in,
                              void* d_out, int out_size)
{
    const float* X      = (const float*)d_in[0];
    const float* attri  = (const float*)d_in[1];
    const float* w_at1  = (const float*)d_in[2];
    const float* b_at1  = (const float*)d_in[3];
    const float* w_at2  = (const float*)d_in[4];
    const float* b_at2  = (const float*)d_in[5];
    const float* w_a1   = (const float*)d_in[6];
    const float* b_a1   = (const float*)d_in[7];
    const float* w_a2   = (const float*)d_in[8];
    const float* b_a2   = (const float*)d_in[9];
    const float* w_ih   = (const float*)d_in[10];
    const float* w_hh   = (const float*)d_in[11];
    const float* b_ih   = (const float*)d_in[12];
    const float* b_hh   = (const float*)d_in[13];
    float* out = (float*)d_out;

    cudaFuncSetAttribute(k_main, cudaFuncAttributeMaxDynamicSharedMemorySize, SMEM_TOTAL);

    k_alpha<<<1, 128>>>(attri, w_at1, b_at1, w_at2, b_at2);
    k_prep<<<(NB * NT * ND + 255) / 256, 256>>>(X, w_ih, w_hh, w_a1, b_ih, b_hh);
    k_gih<<<(NB * NT) / 16 * 1, 256>>>();   // 2048 blocks of 16 rows
    k_xpw<<<NB, 256>>>();
    k_main<<<128, 512, SMEM_TOTAL>>>(b_a1, w_a2, b_a2, out);
}

// round 7
// speedup vs baseline: 4.7512x; 4.7347x over previous
#include <cuda_runtime.h>
#include <cuda_fp16.h>
#include <mma.h>
using namespace nvcuda;

#define NB 512
#define NT 64
#define ND 128
#define NH 128

__device__ float  g_alpha[128];
__device__ __align__(16) float  g_Xa[NB*NT*ND];
__device__ __align__(16) __half g_Xh[NB*NT*ND];
__device__ __align__(16) __half g_wihh[512*128];
__device__ __align__(16) __half g_whhT[128*512];   // [k][g]
__device__ __align__(16) __half g_W1hc[256*128];   // [j][n]
__device__ __align__(16) __half g_W1x[64*128];
__device__ __align__(16) float  g_bsum[512];
__device__ __align__(16) float  g_gih[(size_t)NB*NT*512];
__device__ __align__(16) __half g_XpW[(size_t)NB*128*128];

__device__ __forceinline__ float sigmoidf_(float x) {
    return 1.f / (1.f + __expf(-x));
}
__device__ __forceinline__ float tanh_acc(float x) {
    x = fminf(fmaxf(x, -15.f), 15.f);
    float e2 = __expf(-2.f * x);
    return (1.f - e2) / (1.f + e2);
}
__device__ __forceinline__ __half2 tanh2h(__half2 a) {
    __half2 r;
    asm("tanh.approx.f16x2 %0, %1;" : "=r"(*(unsigned*)&r) : "r"(*(unsigned*)&a));
    return r;
}

__global__ __launch_bounds__(128) void k_alpha(
    const float* __restrict__ attri, const float* __restrict__ w1,
    const float* __restrict__ b1, const float* __restrict__ w2,
    const float* __restrict__ b2)
{
    __shared__ float sv[128];
    __shared__ float sred;
    int d = threadIdx.x;
    float ar[64];
    #pragma unroll
    for (int t = 0; t < 64; ++t) ar[t] = attri[d*64 + t];
    float s = b2[0];
    for (int j = 0; j < 32; ++j) {
        float a = b1[j];
        #pragma unroll
        for (int t = 0; t < 64; ++t) a = fmaf(ar[t], w1[t*32 + j], a);
        a = (a > 0.f) ? a : 0.5f * a;
        s = fmaf(a, w2[j], s);
    }
    sv[d] = s; __syncthreads();
    if (d == 0) { float m = sv[0]; for (int i = 1; i < 128; ++i) m = fmaxf(m, sv[i]); sred = m; }
    __syncthreads();
    float ev = __expf(s - sred);
    sv[d] = ev; __syncthreads();
    if (d == 0) { float su = 0.f; for (int i = 0; i < 128; ++i) su += sv[i]; sred = su; }
    __syncthreads();
    g_alpha[d] = ev / sred;
}

__global__ __launch_bounds__(256) void k_prep(
    const float* __restrict__ X, const float* __restrict__ w_ih,
    const float* __restrict__ w_hh, const float* __restrict__ w_a1,
    const float* __restrict__ b_ih, const float* __restrict__ b_hh)
{
    int i = blockIdx.x * 256 + threadIdx.x;
    if (i < NB*NT*ND) {
        float v = X[i] * g_alpha[i & 127];
        g_Xa[i] = v;
        g_Xh[i] = __float2half(v);
    }
    if (i < 65536) {
        g_wihh[i] = __float2half(w_ih[i]);
        int g = i >> 7, k = i & 127;
        g_whhT[k*512 + g] = __float2half(w_hh[i]);
    }
    if (i < 32768) g_W1hc[i] = __float2half(w_a1[i]);
    if (i < 8192)  g_W1x[i]  = __float2half(w_a1[32768 + i]);
    if (i < 512)   g_bsum[i] = b_ih[i] + b_hh[i];
}

__global__ __launch_bounds__(256) void k_gih()
{
    int m0 = blockIdx.x * 16;
    int w = threadIdx.x >> 5;
    wmma::fragment<wmma::matrix_a, 16, 16, 16, __half, wmma::row_major> a[8];
    #pragma unroll
    for (int k = 0; k < 8; ++k)
        wmma::load_matrix_sync(a[k], g_Xh + (size_t)m0*128 + k*16, 128);
    #pragma unroll
    for (int rep = 0; rep < 4; ++rep) {
        int n0 = w*16 + rep*128;
        wmma::fragment<wmma::accumulator, 16, 16, 16, float> c;
        wmma::fill_fragment(c, 0.f);
        #pragma unroll
        for (int k = 0; k < 8; ++k) {
            wmma::fragment<wmma::matrix_b, 16, 16, 16, __half, wmma::col_major> b;
            wmma::load_matrix_sync(b, g_wihh + (size_t)n0*128 + k*16, 128);
            wmma::mma_sync(c, a[k], b, c);
        }
        wmma::store_matrix_sync(g_gih + (size_t)m0*512 + n0, c, 512, wmma::mem_row_major);
    }
}

__global__ __launch_bounds__(256) void k_xpw()
{
    __shared__ float cbuf[8][256];
    int b = blockIdx.x;
    int w = threadIdx.x >> 5, lane = threadIdx.x & 31;
    const __half* Ab = g_Xh + (size_t)b * (NT*ND);
    int m0 = w * 16;
    wmma::fragment<wmma::matrix_a, 16, 16, 16, __half, wmma::col_major> a[4];
    #pragma unroll
    for (int k = 0; k < 4; ++k)
        wmma::load_matrix_sync(a[k], Ab + k*16*128 + m0, 128);
    for (int nt = 0; nt < 8; ++nt) {
        int n0 = nt * 16;
        wmma::fragment<wmma::accumulator, 16, 16, 16, float> c;
        wmma::fill_fragment(c, 0.f);
        #pragma unroll
        for (int k = 0; k < 4; ++k) {
            wmma::fragment<wmma::matrix_b, 16, 16, 16, __half, wmma::row_major> bb;
            wmma::load_matrix_sync(bb, g_W1x + k*16*128 + n0, 128);
            wmma::mma_sync(c, a[k], bb, c);
        }
        wmma::store_matrix_sync(cbuf[w], c, 16, wmma::mem_row_major);
        __syncwarp();
        #pragma unroll
        for (int j = 0; j < 8; ++j) {
            int idx = j*32 + lane, r = idx >> 4, cl = idx & 15;
            g_XpW[(size_t)b*16384 + (size_t)(m0 + r)*128 + n0 + cl] = __float2half(cbuf[w][idx]);
        }
        __syncwarp();
    }
}

// k_main: padded-smem wmma, 3 sub-phases/step, all 16 warps
#define SW_WHH 520
#define SW_W1  136
#define SW_HA  264
#define SW_GS  260
#define SW_VH  132
#define OFF_WHH  0
#define OFF_W1   133120
#define OFF_HA   202752
#define OFF_GSC  211200
#define OFF_VH   227840
#define OFF_BSUM 228896
#define OFF_BA1  230944
#define OFF_WA2  231456
#define OFF_RED  231968
#define OFF_RED2 232032
#define SMEM_TOTAL 232096

__global__ __launch_bounds__(512, 1) void k_main(
    const float* __restrict__ b_a1, const float* __restrict__ w_a2,
    const float* __restrict__ b_a2p, float* __restrict__ out)
{
    extern __shared__ char sm[];
    __half* s_whh  = (__half*)(sm + OFF_WHH);
    __half* s_w1   = (__half*)(sm + OFF_W1);
    __half* s_hA   = (__half*)(sm + OFF_HA);
    float*  s_gsc  = (float*)(sm + OFF_GSC);
    __half* s_vh   = (__half*)(sm + OFF_VH);
    float*  s_bsum = (float*)(sm + OFF_BSUM);
    float*  s_ba1  = (float*)(sm + OFF_BA1);
    float*  s_wa2  = (float*)(sm + OFF_WA2);
    float*  s_red  = (float*)(sm + OFF_RED);
    float*  s_red2 = (float*)(sm + OFF_RED2);

    const int tid = threadIdx.x, w = tid >> 5, lane = tid & 31;
    const int b0 = blockIdx.x * 4;
    const float b_a2 = b_a2p[0];

    {
        const unsigned* s1 = (const unsigned*)g_whhT;
        unsigned* d1 = (unsigned*)s_whh;
        for (int u = tid; u < 32768; u += 512) {
            int k = u >> 8, g = u & 255;
            d1[k*260 + g] = s1[u];
        }
        const unsigned* s2 = (const unsigned*)g_W1hc;
        unsigned* d2 = (unsigned*)s_w1;
        for (int u = tid; u < 16384; u += 512) {
            int j = u >> 6, n = u & 63;
            d2[j*68 + n] = s2[u];
        }
        unsigned* hz = (unsigned*)s_hA;
        for (int u = tid; u < 2112; u += 512) hz[u] = 0u;
        s_bsum[tid] = g_bsum[tid];
        if (tid < 128) { s_ba1[tid] = b_a1[tid]; s_wa2[tid] = w_a2[tid]; }
    }
    const int b4 = tid >> 7, i = tid & 127;

    __half2 xp[64];
    {
        const __half2* xr = (const __half2*)(g_XpW + ((size_t)(b0 + b4)*128 + i)*128);
        #pragma unroll
        for (int j = 0; j < 64; ++j) xp[j] = xr[j];
    }
    __syncthreads();

    const int vn0 = (w & 7) * 16;   // v tile col
    const int vkh = w >> 3;         // v k-half (0:h, 1:c)
    float creg = 0.f;
    float iis = 0.f, ffc = 0.f;

    for (int t = 0; t < 64; ++t) {
        const size_t grow = ((size_t)(b0 + b4)*64 + t)*512;
        float gp0 = g_gih[grow + i];
        float gp1 = g_gih[grow + 128 + i];
        float gp2 = g_gih[grow + 256 + i];
        float gp3 = g_gih[grow + 384 + i];
        size_t oidx = ((size_t)(b0 + b4)*64 + t)*128 + i;
        float xa = g_Xa[oidx];

        // V: v = [h|c] @ W1hc, K split across warp halves
        {
            wmma::fragment<wmma::accumulator, 16, 16, 16, float> c;
            wmma::fill_fragment(c, 0.f);
            #pragma unroll
            for (int k = 0; k < 8; ++k) {
                wmma::fragment<wmma::matrix_a, 16, 16, 16, __half, wmma::row_major> a;
                wmma::fragment<wmma::matrix_b, 16, 16, 16, __half, wmma::row_major> b;
                wmma::load_matrix_sync(a, s_hA + vkh*128 + k*16, SW_HA);
                wmma::load_matrix_sync(b, s_w1 + (vkh*128 + k*16)*SW_W1 + vn0, SW_W1);
                wmma::mma_sync(c, a, b, c);
            }
            wmma::store_matrix_sync(s_gsc + vkh*128 + vn0, c, SW_GS, wmma::mem_row_major);
        }
        __syncthreads();
        {
            float gv = s_gsc[b4*SW_GS + i] + s_gsc[b4*SW_GS + 128 + i] + s_ba1[i];
            s_vh[b4*SW_VH + i] = __float2half(gv);
        }
        __syncthreads();

        // IF: gate cols 0..255 (i|f), one tile per warp
        {
            wmma::fragment<wmma::accumulator, 16, 16, 16, float> c;
            wmma::fill_fragment(c, 0.f);
            #pragma unroll
            for (int k = 0; k < 8; ++k) {
                wmma::fragment<wmma::matrix_a, 16, 16, 16, __half, wmma::row_major> a;
                wmma::fragment<wmma::matrix_b, 16, 16, 16, __half, wmma::row_major> b;
                wmma::load_matrix_sync(a, s_hA + k*16, SW_HA);
                wmma::load_matrix_sync(b, s_whh + (k*16)*SW_WHH + w*16, SW_WHH);
                wmma::mma_sync(c, a, b, c);
            }
            wmma::store_matrix_sync(s_gsc + w*16, c, SW_GS, wmma::mem_row_major);
        }
        __syncthreads();
        {
            float gi = s_gsc[b4*SW_GS + i] + gp0 + s_bsum[i];
            float gf = s_gsc[b4*SW_GS + 128 + i] + gp1 + s_bsum[128 + i];
            iis = sigmoidf_(gi);
            ffc = sigmoidf_(gf) * creg;
        }
        __syncthreads();

        // GO: gate cols 256..511 (g|o)
        {
            wmma::fragment<wmma::accumulator, 16, 16, 16, float> c;
            wmma::fill_fragment(c, 0.f);
            #pragma unroll
            for (int k = 0; k < 8; ++k) {
                wmma::fragment<wmma::matrix_a, 16, 16, 16, __half, wmma::row_major> a;
                wmma::fragment<wmma::matrix_b, 16, 16, 16, __half, wmma::row_major> b;
                wmma::load_matrix_sync(a, s_hA + k*16, SW_HA);
                wmma::load_matrix_sync(b, s_whh + (k*16)*SW_WHH + 256 + w*16, SW_WHH);
                wmma::mma_sync(c, a, b, c);
            }
            wmma::store_matrix_sync(s_gsc + w*16, c, SW_GS, wmma::mem_row_major);
        }
        __syncthreads();
        {
            float gg = s_gsc[b4*SW_GS + i] + gp2 + s_bsum[256 + i];
            float go = s_gsc[b4*SW_GS + 128 + i] + gp3 + s_bsum[384 + i];
            creg = ffc + iis * tanh_acc(gg);
            float hn = sigmoidf_(go) * tanh_acc(creg);
            s_hA[b4*SW_HA + i] = __float2half(hn);
            s_hA[b4*SW_HA + 128 + i] = __float2half(creg);
        }

        // phase B: e = w2 . tanh(xp + v) + b2, softmax over d, output
        {
            const __half2* vr = (const __half2*)(s_vh + b4*SW_VH);
            const float2* w2p = (const float2*)s_wa2;
            float acc = b_a2;
            #pragma unroll 16
            for (int k2 = 0; k2 < 64; ++k2) {
                __half2 th = tanh2h(__hadd2(xp[k2], vr[k2]));
                float2 tf = __half22float2(th);
                float2 ww = w2p[k2];
                acc = fmaf(tf.x, ww.x, fmaf(tf.y, ww.y, acc));
            }
            float m = acc;
            #pragma unroll
            for (int o = 16; o > 0; o >>= 1) m = fmaxf(m, __shfl_xor_sync(0xffffffffu, m, o));
            int wq = (tid >> 5) & 3;
            if (lane == 0) s_red[b4*4 + wq] = m;
            __syncthreads();
            float gm = fmaxf(fmaxf(s_red[b4*4], s_red[b4*4 + 1]),
                             fmaxf(s_red[b4*4 + 2], s_red[b4*4 + 3]));
            float ex = __expf(acc - gm);
            float ss = ex;
            #pragma unroll
            for (int o = 16; o > 0; o >>= 1) ss += __shfl_xor_sync(0xffffffffu, ss, o);
            if (lane == 0) s_red2[b4*4 + wq] = ss;
            __syncthreads();
            float tot = s_red2[b4*4] + s_red2[b4*4 + 1] + s_red2[b4*4 + 2] + s_red2[b4*4 + 3];
            out[oidx] = (ex / tot) * xa;
        }
    }
}

extern "C" void kernel_launch(void* const* d_in, const int* in_sizes, int n_in,
                              void* d_out, int out_size)
{
    const float* X     = (const float*)d_in[0];
    const float* attri = (const float*)d_in[1];
    const float* w_at1 = (const float*)d_in[2];
    const float* b_at1 = (const float*)d_in[3];
    const float* w_at2 = (const float*)d_in[4];
    const float* b_at2 = (const float*)d_in[5];
    const float* w_a1  = (const float*)d_in[6];
    const float* b_a1  = (const float*)d_in[7];
    const float* w_a2  = (const float*)d_in[8];
    const float* b_a2  = (const float*)d_in[9];
    const float* w_ih  = (const float*)d_in[10];
    const float* w_hh  = (const float*)d_in[11];
    const float* b_ih  = (const float*)d_in[12];
    const float* b_hh  = (const float*)d_in[13];
    float* out = (float*)d_out;

    cudaFuncSetAttribute(k_main, cudaFuncAttributeMaxDynamicSharedMemorySize, SMEM_TOTAL);
    k_alpha<<<1, 128>>>(attri, w_at1, b_at1, w_at2, b_at2);
    k_prep<<<(NB*NT*ND + 255)/256, 256>>>(X, w_ih, w_hh, w_a1, b_ih, b_hh);
    k_gih<<<(NB*NT)/16, 256>>>();
    k_xpw<<<NB, 256>>>();
    k_main<<<128, 512, SMEM_TOTAL>>>(b_a1, w_a2, b_a2, out);
}